// round 16
// baseline (speedup 1.0000x reference)
#include <cuda_runtime.h>
#include <cuda_fp16.h>
#include <cstdint>

// Constants from the reference
#define EPS     1e-10f
#define B_CONST (1.0f + 0.1f + 0.05f)   // 1.15
#define BR      (1.0f + 0.1f - 0.05f)   // 1.05
#define HW      (512 * 512)

// Packed table: half2(v, 1/(v+EPS)) = 4 B/entry -> 1 MB total.
__device__ __half2 g_vv[HW];

// Table build: 4 pixels/thread; writes four half2 entries as one uint4.
// Early PDL trigger releases the dependent loss grid at store-drain.
__global__ void __launch_bounds__(256) build_v_kernel(const float4* __restrict__ vin4,
                                                      float* __restrict__ out) {
    int t = blockIdx.x * blockDim.x + threadIdx.x;
    if (t < HW / 4) {
        float4 a = vin4[t];
        float4 b = vin4[t + HW / 4];
        float4 c = vin4[t + 2 * (HW / 4)];

        float v0 = ((a.x + b.x + c.x) * (1.0f/3.0f) * 255.0f + 1.0f) * (1.0f/256.0f);
        float v1 = ((a.y + b.y + c.y) * (1.0f/3.0f) * 255.0f + 1.0f) * (1.0f/256.0f);
        float v2 = ((a.z + b.z + c.z) * (1.0f/3.0f) * 255.0f + 1.0f) * (1.0f/256.0f);
        float v3 = ((a.w + b.w + c.w) * (1.0f/3.0f) * 255.0f + 1.0f) * (1.0f/256.0f);

        __half2 h0 = __floats2half2_rn(v0, __frcp_rn(v0 + EPS));
        __half2 h1 = __floats2half2_rn(v1, __frcp_rn(v1 + EPS));
        __half2 h2 = __floats2half2_rn(v2, __frcp_rn(v2 + EPS));
        __half2 h3 = __floats2half2_rn(v3, __frcp_rn(v3 + EPS));

        uint4 packed;
        packed.x = *reinterpret_cast<uint32_t*>(&h0);
        packed.y = *reinterpret_cast<uint32_t*>(&h1);
        packed.z = *reinterpret_cast<uint32_t*>(&h2);
        packed.w = *reinterpret_cast<uint32_t*>(&h3);
        reinterpret_cast<uint4*>(g_vv)[t] = packed;
    }
    if (t == 0) out[0] = 0.0f;

    cudaTriggerProgrammaticLaunchCompletion();
}

// Loss kernel: R15 winner with __ldcs on streaming loads (evict-streaming)
// so the 1 MB gather table keeps maximum L1D residency.
__global__ void __launch_bounds__(256) whdr_loss_kernel(
    const int4*  __restrict__ coords,    // (N,4) int32 as int4: x1,y1,x2,y2
    const int*   __restrict__ darker,    // (N,)
    const float* __restrict__ weights,   // (N,)
    float* __restrict__ out,
    int n)
{
    cudaGridDependencySynchronize();     // wait for build_v_kernel (PDL)

    const float inv_b = 1.0f / B_CONST;
    const float bl    = 1.0f / BR;
    const float inv_n = 1.0f / (float)n;

    float acc = 0.0f;

    int stride = gridDim.x * blockDim.x;
    #pragma unroll 4
    for (int i = blockIdx.x * blockDim.x + threadIdx.x; i < n; i += stride) {
        int4 c  = __ldcs(&coords[i]);
        int  d  = __ldcs(&darker[i]);
        float w = __ldcs(&weights[i]);

        int i1 = (c.y << 9) | c.x;   // y1*512 + x1
        int i2 = (c.w << 9) | c.z;   // y2*512 + x2

        float2 p1 = __half22float2(__ldg(&g_vv[i1]));   // (r1, 1/(r1+eps))
        float2 p2 = __half22float2(__ldg(&g_vv[i2]));   // (r2, 1/(r2+eps))

        float ratio     = p1.x * p2.y;  // r1 / (r2 + EPS)
        float ratio_inv = p2.x * p1.y;  // r2 / (r1 + EPS)

        float l1 = (ratio > inv_b)   ? (ratio - inv_b + (B_CONST - ratio_inv)) : 0.0f;
        float l2 = (ratio < B_CONST) ? (B_CONST - ratio + (ratio_inv - inv_b)) : 0.0f;
        float l0 = (ratio > BR) ? (ratio - BR + (bl - ratio_inv))
                 : ((ratio < bl) ? (bl - ratio + (ratio_inv - BR)) : 0.0f);

        float per = (d == 1) ? l1 : ((d == 2) ? l2 : l0);
        acc += w * per;
    }

    // Warp reduction
    #pragma unroll
    for (int off = 16; off > 0; off >>= 1)
        acc += __shfl_xor_sync(0xffffffffu, acc, off);

    // Block reduction
    __shared__ float warp_sums[8];
    int lane = threadIdx.x & 31;
    int wid  = threadIdx.x >> 5;
    if (lane == 0) warp_sums[wid] = acc;
    __syncthreads();
    if (wid == 0) {
        float s = (lane < (blockDim.x >> 5)) ? warp_sums[lane] : 0.0f;
        #pragma unroll
        for (int off = 4; off > 0; off >>= 1)
            s += __shfl_xor_sync(0xffffffffu, s, off);
        if (lane == 0)
            atomicAdd(out, s * inv_n);
    }
}

extern "C" void kernel_launch(void* const* d_in, const int* in_sizes, int n_in,
                              void* d_out, int out_size)
{
    const float4* vin4    = (const float4*)d_in[0];
    const int4*   coords  = (const int4*)d_in[1];
    const int*    darker  = (const int*)d_in[2];
    const float*  weights = (const float*)d_in[3];
    float*        out     = (float*)d_out;

    int n = in_sizes[2];  // darker element count == N

    build_v_kernel<<<(HW / 4 + 255) / 256, 256>>>(vin4, out);

    // PDL launch: overlaps launch/setup with build_v_kernel's execution.
    cudaLaunchConfig_t cfg = {};
    cfg.gridDim  = dim3(2048, 1, 1);   // 16 elts/thread, exact fit for N=8388608
    cfg.blockDim = dim3(256, 1, 1);
    cudaLaunchAttribute attrs[1];
    attrs[0].id = cudaLaunchAttributeProgrammaticStreamSerialization;
    attrs[0].val.programmaticStreamSerializationAllowed = 1;
    cfg.attrs    = attrs;
    cfg.numAttrs = 1;
    cudaLaunchKernelEx(&cfg, whdr_loss_kernel, coords, darker, weights, out, n);
}

// round 17
// speedup vs baseline: 1.0066x; 1.0066x over previous
#include <cuda_runtime.h>
#include <cuda_fp16.h>
#include <cstdint>

// Constants from the reference
#define EPS     1e-10f
#define B_CONST (1.0f + 0.1f + 0.05f)   // 1.15
#define BR      (1.0f + 0.1f - 0.05f)   // 1.05
#define HW      (512 * 512)

// Packed table: half2(v, 1/(v+EPS)) = 4 B/entry -> 1 MB total.
__device__ __half2 g_vv[HW];

// Table build: 4 pixels/thread; writes four half2 entries as one uint4.
// Early PDL trigger releases the dependent loss grid at store-drain.
__global__ void __launch_bounds__(256) build_v_kernel(const float4* __restrict__ vin4,
                                                      float* __restrict__ out) {
    int t = blockIdx.x * blockDim.x + threadIdx.x;
    if (t < HW / 4) {
        float4 a = vin4[t];
        float4 b = vin4[t + HW / 4];
        float4 c = vin4[t + 2 * (HW / 4)];

        float v0 = ((a.x + b.x + c.x) * (1.0f/3.0f) * 255.0f + 1.0f) * (1.0f/256.0f);
        float v1 = ((a.y + b.y + c.y) * (1.0f/3.0f) * 255.0f + 1.0f) * (1.0f/256.0f);
        float v2 = ((a.z + b.z + c.z) * (1.0f/3.0f) * 255.0f + 1.0f) * (1.0f/256.0f);
        float v3 = ((a.w + b.w + c.w) * (1.0f/3.0f) * 255.0f + 1.0f) * (1.0f/256.0f);

        __half2 h0 = __floats2half2_rn(v0, __frcp_rn(v0 + EPS));
        __half2 h1 = __floats2half2_rn(v1, __frcp_rn(v1 + EPS));
        __half2 h2 = __floats2half2_rn(v2, __frcp_rn(v2 + EPS));
        __half2 h3 = __floats2half2_rn(v3, __frcp_rn(v3 + EPS));

        uint4 packed;
        packed.x = *reinterpret_cast<uint32_t*>(&h0);
        packed.y = *reinterpret_cast<uint32_t*>(&h1);
        packed.z = *reinterpret_cast<uint32_t*>(&h2);
        packed.w = *reinterpret_cast<uint32_t*>(&h3);
        reinterpret_cast<uint4*>(g_vv)[t] = packed;
    }
    if (t == 0) out[0] = 0.0f;

    cudaTriggerProgrammaticLaunchCompletion();
}

// Loss kernel: R16 body (best: 64.5us); 4096 blocks x 8 elts/thread for a
// finer wave-tail quantum (exact fit: 4096*256*8 = 8388608 = N).
__global__ void __launch_bounds__(256) whdr_loss_kernel(
    const int4*  __restrict__ coords,    // (N,4) int32 as int4: x1,y1,x2,y2
    const int*   __restrict__ darker,    // (N,)
    const float* __restrict__ weights,   // (N,)
    float* __restrict__ out,
    int n)
{
    cudaGridDependencySynchronize();     // wait for build_v_kernel (PDL)

    const float inv_b = 1.0f / B_CONST;
    const float bl    = 1.0f / BR;
    const float inv_n = 1.0f / (float)n;

    float acc = 0.0f;

    int stride = gridDim.x * blockDim.x;
    #pragma unroll 4
    for (int i = blockIdx.x * blockDim.x + threadIdx.x; i < n; i += stride) {
        int4 c  = __ldcs(&coords[i]);
        int  d  = __ldcs(&darker[i]);
        float w = __ldcs(&weights[i]);

        int i1 = (c.y << 9) | c.x;   // y1*512 + x1
        int i2 = (c.w << 9) | c.z;   // y2*512 + x2

        float2 p1 = __half22float2(__ldg(&g_vv[i1]));   // (r1, 1/(r1+eps))
        float2 p2 = __half22float2(__ldg(&g_vv[i2]));   // (r2, 1/(r2+eps))

        float ratio     = p1.x * p2.y;  // r1 / (r2 + EPS)
        float ratio_inv = p2.x * p1.y;  // r2 / (r1 + EPS)

        float l1 = (ratio > inv_b)   ? (ratio - inv_b + (B_CONST - ratio_inv)) : 0.0f;
        float l2 = (ratio < B_CONST) ? (B_CONST - ratio + (ratio_inv - inv_b)) : 0.0f;
        float l0 = (ratio > BR) ? (ratio - BR + (bl - ratio_inv))
                 : ((ratio < bl) ? (bl - ratio + (ratio_inv - BR)) : 0.0f);

        float per = (d == 1) ? l1 : ((d == 2) ? l2 : l0);
        acc += w * per;
    }

    // Warp reduction
    #pragma unroll
    for (int off = 16; off > 0; off >>= 1)
        acc += __shfl_xor_sync(0xffffffffu, acc, off);

    // Block reduction
    __shared__ float warp_sums[8];
    int lane = threadIdx.x & 31;
    int wid  = threadIdx.x >> 5;
    if (lane == 0) warp_sums[wid] = acc;
    __syncthreads();
    if (wid == 0) {
        float s = (lane < (blockDim.x >> 5)) ? warp_sums[lane] : 0.0f;
        #pragma unroll
        for (int off = 4; off > 0; off >>= 1)
            s += __shfl_xor_sync(0xffffffffu, s, off);
        if (lane == 0)
            atomicAdd(out, s * inv_n);
    }
}

extern "C" void kernel_launch(void* const* d_in, const int* in_sizes, int n_in,
                              void* d_out, int out_size)
{
    const float4* vin4    = (const float4*)d_in[0];
    const int4*   coords  = (const int4*)d_in[1];
    const int*    darker  = (const int*)d_in[2];
    const float*  weights = (const float*)d_in[3];
    float*        out     = (float*)d_out;

    int n = in_sizes[2];  // darker element count == N

    build_v_kernel<<<(HW / 4 + 255) / 256, 256>>>(vin4, out);

    // PDL launch: overlaps launch/setup with build_v_kernel's execution.
    cudaLaunchConfig_t cfg = {};
    cfg.gridDim  = dim3(4096, 1, 1);   // 8 elts/thread, exact fit for N=8388608
    cfg.blockDim = dim3(256, 1, 1);
    cudaLaunchAttribute attrs[1];
    attrs[0].id = cudaLaunchAttributeProgrammaticStreamSerialization;
    attrs[0].val.programmaticStreamSerializationAllowed = 1;
    cfg.attrs    = attrs;
    cfg.numAttrs = 1;
    cudaLaunchKernelEx(&cfg, whdr_loss_kernel, coords, darker, weights, out, n);
}